// round 3
// baseline (speedup 1.0000x reference)
#include <cuda_runtime.h>
#include <cuda_bf16.h>
#include <cstdint>

#define EE 16384
#define NNODE 4096
#define HC 16384

// ------------- static scratch -------------
__device__ __align__(16) float g_XLR[(size_t)NNODE * 32768];  // [n][0:16384)=x_l, [16384:32768)=x_r
__device__ __align__(16) float g_R[(size_t)NNODE * HC];       // relu(agg + bias)
__device__ uint4 g_ApackHi[256 * 4 * 32];
__device__ uint4 g_ApackLo[256 * 4 * 32];
__device__ __align__(16) unsigned g_WpackHi[2 * 4 * 16384 * 8];
__device__ __align__(16) unsigned g_WpackLo[2 * 4 * 16384 * 8];
__device__ int g_deg[NNODE];
__device__ int g_rowptr[NNODE + 1];
__device__ int g_cursor[NNODE];
__device__ int g_esrc[EE];
__device__ int g_is64;
__device__ int g_src[EE];
__device__ int g_dstA[EE];

// ------------- helpers -------------
__device__ __forceinline__ void split2(float f0, float f1, unsigned &hi, unsigned &lo) {
    __nv_bfloat162 hv = __floats2bfloat162_rn(f0, f1);
    hi = *reinterpret_cast<unsigned *>(&hv);
    __nv_bfloat162 lv = __floats2bfloat162_rn(f0 - __low2float(hv), f1 - __high2float(hv));
    lo = *reinterpret_cast<unsigned *>(&lv);
}
__device__ __forceinline__ void mma_bf16(float &c0, float &c1, float &c2, float &c3,
                                         unsigned a0, unsigned a1, unsigned a2, unsigned a3,
                                         unsigned b0, unsigned b1) {
    asm volatile("mma.sync.aligned.m16n8k16.row.col.f32.bf16.bf16.f32 "
                 "{%0,%1,%2,%3}, {%4,%5,%6,%7}, {%8,%9}, {%0,%1,%2,%3};\n"
                 : "+f"(c0), "+f"(c1), "+f"(c2), "+f"(c3)
                 : "r"(a0), "r"(a1), "r"(a2), "r"(a3), "r"(b0), "r"(b1));
}
__device__ __forceinline__ float lrelu(float v) { return fmaxf(v, 0.f) + 0.2f * fminf(v, 0.f); }

// ------------- edge_index dtype detection + sanitized extraction -------------
__global__ void detect_k(const unsigned *__restrict__ w) {
    int is64 = 1;
    for (int i = 1; i < 64; i += 2)
        if (w[i] != 0u) { is64 = 0; break; }
    g_is64 = is64;
}
__global__ void loadidx_k(const unsigned *__restrict__ w) {
    int e = blockIdx.x * 256 + threadIdx.x;
    if (e < EE) {
        int s, d;
        if (g_is64) {  // int64 little-endian, values < 2^31: take low words
            s = (int)w[2 * e];
            d = (int)w[2 * (EE + e)];
        } else {       // int32
            s = (int)w[e];
            d = (int)w[EE + e];
        }
        g_src[e] = s & (NNODE - 1);   // clamp-mask: guaranteed in-range
        g_dstA[e] = d & (NNODE - 1);
    }
}

// ------------- pack A (x) into mma fragments -------------
__global__ void pack_a_k(const float *__restrict__ x) {
    int t = blockIdx.x * 256 + threadIdx.x;  // 32768 threads
    int lane = t & 31, kt = (t >> 5) & 3, mt = t >> 7;
    int gid = lane >> 2, tig = lane & 3;
    int r0 = mt * 16 + gid, r1 = r0 + 8;
    int c0 = kt * 16 + tig * 2, c1 = c0 + 8;
    uint4 hi, lo;
    split2(x[r0 * 64 + c0], x[r0 * 64 + c0 + 1], hi.x, lo.x);
    split2(x[r1 * 64 + c0], x[r1 * 64 + c0 + 1], hi.y, lo.y);
    split2(x[r0 * 64 + c1], x[r0 * 64 + c1 + 1], hi.z, lo.z);
    split2(x[r1 * 64 + c1], x[r1 * 64 + c1 + 1], hi.w, lo.w);
    g_ApackHi[(mt * 4 + kt) * 32 + lane] = hi;
    g_ApackLo[(mt * 4 + kt) * 32 + lane] = lo;
}

// ------------- pack W_l/W_r into B fragments -------------
__global__ void pack_w_k(const float *__restrict__ Wl, const float *__restrict__ Wr) {
    unsigned t = blockIdx.x * 256u + threadIdx.x;  // 1,048,576 threads exactly
    unsigned mat = t >> 19, idx = t & 524287u;
    unsigned kt = idx >> 17, rem = idx & 131071u;
    unsigned n = rem >> 3, j = rem & 7;
    unsigned q = j >> 1, s = j & 1;
    unsigned k = kt * 16 + s * 8 + q * 2;
    const float *W = mat ? Wr : Wl;
    unsigned hi, lo;
    split2(W[k * HC + n], W[(k + 1) * HC + n], hi, lo);
    g_WpackHi[t] = hi;
    g_WpackLo[t] = lo;
}

// ------------- CSR by destination -------------
__global__ void zero_deg_k() {
    int t = blockIdx.x * 256 + threadIdx.x;
    if (t < NNODE) g_deg[t] = 0;
}
__global__ void hist_k() {
    int e = blockIdx.x * 256 + threadIdx.x;
    if (e < EE) atomicAdd(&g_deg[g_dstA[e]], 1);
}
__global__ void scan_k() {
    __shared__ int sm[1024];
    int t = threadIdx.x, b = t * 4;
    int d0 = g_deg[b], d1 = g_deg[b + 1], d2 = g_deg[b + 2], d3 = g_deg[b + 3];
    int p1 = d0, p2 = d0 + d1, p3 = p2 + d2, tot = p3 + d3;
    sm[t] = tot;
    __syncthreads();
    for (int off = 1; off < 1024; off <<= 1) {
        int y = (t >= off) ? sm[t - off] : 0;
        __syncthreads();
        sm[t] += y;
        __syncthreads();
    }
    int excl = (t > 0) ? sm[t - 1] : 0;
    g_rowptr[b] = excl;          g_cursor[b] = excl;
    g_rowptr[b + 1] = excl + p1; g_cursor[b + 1] = excl + p1;
    g_rowptr[b + 2] = excl + p2; g_cursor[b + 2] = excl + p2;
    g_rowptr[b + 3] = excl + p3; g_cursor[b + 3] = excl + p3;
    if (t == 1023) g_rowptr[NNODE] = sm[1023];
}
__global__ void scatter_k() {
    int e = blockIdx.x * 256 + threadIdx.x;
    if (e < EE) {
        int dst = g_dstA[e];
        g_esrc[atomicAdd(&g_cursor[dst], 1)] = g_src[e];
    }
}

// ------------- GEMM: XLR = x @ [W_l | W_r] (bf16 hi/lo split mma) -------------
__global__ void __launch_bounds__(256) gemm_k() {
    __shared__ uint4 sB[1024];  // hi [0,512), lo [512,1024)
    int t = threadIdx.x;
    int n0 = blockIdx.x * 64;
    int mat = (n0 >= HC) ? 1 : 0;
    int nn = n0 - mat * HC;
    const uint4 *Vh = ((const uint4 *)g_WpackHi) + (size_t)mat * 131072;
    const uint4 *Vl = ((const uint4 *)g_WpackLo) + (size_t)mat * 131072;
#pragma unroll
    for (int i = 0; i < 4; i++) {
        int idx = i * 256 + t;
        int isLo = idx >> 9, w = idx & 511;
        int kt = w >> 7, u = w & 127;
        const uint4 *src = isLo ? Vl : Vh;
        sB[isLo * 512 + kt * 128 + u] = src[(kt * 16384 + nn) * 2 + u];
    }
    int warp = t >> 5, lane = t & 31;
    int gid = lane >> 2, tig = lane & 3;
    int mt = blockIdx.y * 8 + warp;
    uint4 aH[4], aL[4];
#pragma unroll
    for (int kt = 0; kt < 4; kt++) {
        aH[kt] = g_ApackHi[(mt * 4 + kt) * 32 + lane];
        aL[kt] = g_ApackLo[(mt * 4 + kt) * 32 + lane];
    }
    __syncthreads();
    const unsigned *sH = (const unsigned *)sB;
    const unsigned *sL = sH + 2048;
    size_t rowoff = (size_t)(mt * 16 + gid) * 32768 + n0;
    float *o0 = g_XLR + rowoff;
    float *o1 = g_XLR + rowoff + (size_t)8 * 32768;
#pragma unroll
    for (int nt = 0; nt < 8; nt++) {
        float c0 = 0.f, c1 = 0.f, c2 = 0.f, c3 = 0.f;
#pragma unroll
        for (int kt = 0; kt < 4; kt++) {
            int bi = kt * 512 + (nt * 8 + gid) * 8 + tig * 2;
            unsigned bh0 = sH[bi], bh1 = sH[bi + 1];
            unsigned bl0 = sL[bi], bl1 = sL[bi + 1];
            mma_bf16(c0, c1, c2, c3, aH[kt].x, aH[kt].y, aH[kt].z, aH[kt].w, bh0, bh1);
            mma_bf16(c0, c1, c2, c3, aH[kt].x, aH[kt].y, aH[kt].z, aH[kt].w, bl0, bl1);
            mma_bf16(c0, c1, c2, c3, aL[kt].x, aL[kt].y, aL[kt].z, aL[kt].w, bh0, bh1);
        }
        int col = nt * 8 + tig * 2;
        *(float2 *)(o0 + col) = make_float2(c0, c1);
        *(float2 *)(o1 + col) = make_float2(c2, c3);
    }
}

// ------------- fused attention: logits + online softmax + agg + bias + relu -------------
__global__ void __launch_bounds__(128) attn_k(const float *__restrict__ att,
                                              const float *__restrict__ bias) {
    int dst = blockIdx.x, h = blockIdx.y;
    int t = threadIdx.x, warp = t >> 5, lane = t & 31;
    const float4 *xr4 = (const float4 *)(g_XLR + (size_t)dst * 32768 + HC + h * 1024);
    float4 xrA = xr4[t], xrB = xr4[t + 128];
    const float4 *at4 = (const float4 *)(att + h * 1024);
    float4 atA = at4[t], atB = at4[t + 128];
    float4 accA = make_float4(0.f, 0.f, 0.f, 0.f), accB = accA;
    float m = -1e30f, s = 0.f;
    __shared__ float red[4];
    int rp = g_rowptr[dst];
    int deg = g_rowptr[dst + 1] - rp;
    for (int i = 0; i <= deg; i++) {  // last = self-loop
        int src = (i < deg) ? g_esrc[rp + i] : dst;
        const float4 *xl4 = (const float4 *)(g_XLR + (size_t)src * 32768 + h * 1024);
        float4 xlA = xl4[t], xlB = xl4[t + 128];
        float p = atA.x * lrelu(xlA.x + xrA.x);
        p = fmaf(atA.y, lrelu(xlA.y + xrA.y), p);
        p = fmaf(atA.z, lrelu(xlA.z + xrA.z), p);
        p = fmaf(atA.w, lrelu(xlA.w + xrA.w), p);
        p = fmaf(atB.x, lrelu(xlB.x + xrB.x), p);
        p = fmaf(atB.y, lrelu(xlB.y + xrB.y), p);
        p = fmaf(atB.z, lrelu(xlB.z + xrB.z), p);
        p = fmaf(atB.w, lrelu(xlB.w + xrB.w), p);
        p += __shfl_xor_sync(0xffffffffu, p, 16);
        p += __shfl_xor_sync(0xffffffffu, p, 8);
        p += __shfl_xor_sync(0xffffffffu, p, 4);
        p += __shfl_xor_sync(0xffffffffu, p, 2);
        p += __shfl_xor_sync(0xffffffffu, p, 1);
        if (lane == 0) red[warp] = p;
        __syncthreads();
        float l = red[0] + red[1] + red[2] + red[3];
        float mn = fmaxf(m, l);
        float sc = __expf(m - mn);
        float w = __expf(l - mn);
        s = s * sc + w;
        accA.x = fmaf(accA.x, sc, w * xlA.x);
        accA.y = fmaf(accA.y, sc, w * xlA.y);
        accA.z = fmaf(accA.z, sc, w * xlA.z);
        accA.w = fmaf(accA.w, sc, w * xlA.w);
        accB.x = fmaf(accB.x, sc, w * xlB.x);
        accB.y = fmaf(accB.y, sc, w * xlB.y);
        accB.z = fmaf(accB.z, sc, w * xlB.z);
        accB.w = fmaf(accB.w, sc, w * xlB.w);
        m = mn;
        __syncthreads();
    }
    float inv = 1.f / (s + 1e-16f);
    const float4 *b4 = (const float4 *)(bias + h * 1024);
    float4 bA = b4[t], bB = b4[t + 128];
    float4 oA, oB;
    oA.x = fmaxf(fmaf(accA.x, inv, bA.x), 0.f);
    oA.y = fmaxf(fmaf(accA.y, inv, bA.y), 0.f);
    oA.z = fmaxf(fmaf(accA.z, inv, bA.z), 0.f);
    oA.w = fmaxf(fmaf(accA.w, inv, bA.w), 0.f);
    oB.x = fmaxf(fmaf(accB.x, inv, bB.x), 0.f);
    oB.y = fmaxf(fmaf(accB.y, inv, bB.y), 0.f);
    oB.z = fmaxf(fmaf(accB.z, inv, bB.z), 0.f);
    oB.w = fmaxf(fmaf(accB.w, inv, bB.w), 0.f);
    float4 *Ro = (float4 *)(g_R + (size_t)dst * HC + h * 1024);
    Ro[t] = oA;
    Ro[t + 128] = oB;
}

// ------------- output GEMM: z = R @ W_out + b_out -------------
__global__ void zinit_k(float *__restrict__ out, const float *__restrict__ bout) {
    int i = blockIdx.x * 256 + threadIdx.x;  // 81920 exactly
    out[i] = bout[i % 20];
}
__global__ void __launch_bounds__(128) zout_k(const float *__restrict__ Wout,
                                              float *__restrict__ out) {
    __shared__ float4 sW[640];  // 128 k-rows x 20 floats
    int t = threadIdx.x;
    int row0 = blockIdx.x * 256 + t;  // rows row0, row0+128
    int kb = blockIdx.y * 2048;
    float acc0[20], acc1[20];
#pragma unroll
    for (int j = 0; j < 20; j++) { acc0[j] = 0.f; acc1[j] = 0.f; }
    const float4 *R0 = (const float4 *)(g_R + (size_t)row0 * HC + kb);
    const float4 *R1 = (const float4 *)(g_R + (size_t)(row0 + 128) * HC + kb);
    for (int ch = 0; ch < 16; ch++) {
        __syncthreads();
        const float4 *Wg = (const float4 *)(Wout + (size_t)(kb + ch * 128) * 20);
        for (int i = t; i < 640; i += 128) sW[i] = Wg[i];
        __syncthreads();
#pragma unroll 4
        for (int i4 = 0; i4 < 32; i4++) {
            float4 r0 = R0[ch * 32 + i4];
            float4 r1 = R1[ch * 32 + i4];
            const float4 *wrow = sW + i4 * 20;
            const float *rv0 = (const float *)&r0;
            const float *rv1 = (const float *)&r1;
#pragma unroll
            for (int kk = 0; kk < 4; kk++) {
                float a = rv0[kk], b = rv1[kk];
#pragma unroll
                for (int q = 0; q < 5; q++) {
                    float4 w = wrow[kk * 5 + q];
                    acc0[q * 4 + 0] = fmaf(a, w.x, acc0[q * 4 + 0]);
                    acc0[q * 4 + 1] = fmaf(a, w.y, acc0[q * 4 + 1]);
                    acc0[q * 4 + 2] = fmaf(a, w.z, acc0[q * 4 + 2]);
                    acc0[q * 4 + 3] = fmaf(a, w.w, acc0[q * 4 + 3]);
                    acc1[q * 4 + 0] = fmaf(b, w.x, acc1[q * 4 + 0]);
                    acc1[q * 4 + 1] = fmaf(b, w.y, acc1[q * 4 + 1]);
                    acc1[q * 4 + 2] = fmaf(b, w.z, acc1[q * 4 + 2]);
                    acc1[q * 4 + 3] = fmaf(b, w.w, acc1[q * 4 + 3]);
                }
            }
        }
    }
#pragma unroll
    for (int j = 0; j < 20; j++) {
        atomicAdd(&out[row0 * 20 + j], acc0[j]);
        atomicAdd(&out[(row0 + 128) * 20 + j], acc1[j]);
    }
}

extern "C" void kernel_launch(void *const *d_in, const int *in_sizes, int n_in,
                              void *d_out, int out_size) {
    const float *x = (const float *)d_in[0];
    const unsigned *ei = (const unsigned *)d_in[1];
    const float *Wl = (const float *)d_in[2];
    const float *Wr = (const float *)d_in[3];
    const float *att = (const float *)d_in[4];
    const float *bias = (const float *)d_in[5];
    const float *Wout = (const float *)d_in[6];
    const float *bout = (const float *)d_in[7];
    float *out = (float *)d_out;

    detect_k<<<1, 1>>>(ei);
    loadidx_k<<<64, 256>>>(ei);
    pack_a_k<<<128, 256>>>(x);
    pack_w_k<<<4096, 256>>>(Wl, Wr);
    zero_deg_k<<<16, 256>>>();
    hist_k<<<64, 256>>>();
    scan_k<<<1, 1024>>>();
    scatter_k<<<64, 256>>>();
    gemm_k<<<dim3(512, 32), 256>>>();
    zinit_k<<<320, 256>>>(out, bout);
    attn_k<<<dim3(4096, 16), 128>>>(att, bias);
    zout_k<<<dim3(16, 8), 128>>>(Wout, out);
}

// round 4
// speedup vs baseline: 1.1351x; 1.1351x over previous
#include <cuda_runtime.h>
#include <cuda_bf16.h>
#include <cuda_fp16.h>
#include <cstdint>

#define EE 16384
#define NNODE 4096
#define HC 16384

// ------------- static scratch -------------
__device__ __align__(16) __half g_XLRh[(size_t)NNODE * 32768];  // fp16: [n][0:16384)=x_l, [16384:)=x_r
__device__ __align__(16) __half g_Rh[(size_t)NNODE * HC];       // fp16: relu(agg + bias)
__device__ uint4 g_ApackHi[256 * 4 * 32];
__device__ uint4 g_ApackLo[256 * 4 * 32];
__device__ __align__(16) unsigned g_WpackHi[2 * 4 * 16384 * 8];
__device__ __align__(16) unsigned g_WpackLo[2 * 4 * 16384 * 8];
__device__ int g_deg[NNODE];
__device__ int g_rowptr[NNODE + 1];
__device__ int g_cursor[NNODE];
__device__ int g_esrc[EE];
__device__ int g_is64;
__device__ int g_src[EE];
__device__ int g_dstA[EE];

// ------------- helpers -------------
__device__ __forceinline__ void split2(float f0, float f1, unsigned &hi, unsigned &lo) {
    __nv_bfloat162 hv = __floats2bfloat162_rn(f0, f1);
    hi = *reinterpret_cast<unsigned *>(&hv);
    __nv_bfloat162 lv = __floats2bfloat162_rn(f0 - __low2float(hv), f1 - __high2float(hv));
    lo = *reinterpret_cast<unsigned *>(&lv);
}
__device__ __forceinline__ void mma_bf16(float &c0, float &c1, float &c2, float &c3,
                                         unsigned a0, unsigned a1, unsigned a2, unsigned a3,
                                         unsigned b0, unsigned b1) {
    asm volatile("mma.sync.aligned.m16n8k16.row.col.f32.bf16.bf16.f32 "
                 "{%0,%1,%2,%3}, {%4,%5,%6,%7}, {%8,%9}, {%0,%1,%2,%3};\n"
                 : "+f"(c0), "+f"(c1), "+f"(c2), "+f"(c3)
                 : "r"(a0), "r"(a1), "r"(a2), "r"(a3), "r"(b0), "r"(b1));
}
__device__ __forceinline__ float lrelu(float v) { return fmaxf(v, 0.f) + 0.2f * fminf(v, 0.f); }
__device__ __forceinline__ void h8_to_f(const uint4 &u, float *f) {
    const __half2 *p = (const __half2 *)&u;
#pragma unroll
    for (int i = 0; i < 4; i++) {
        float2 v = __half22float2(p[i]);
        f[2 * i] = v.x;
        f[2 * i + 1] = v.y;
    }
}

// ------------- edge_index dtype detection + sanitized extraction -------------
__global__ void detect_k(const unsigned *__restrict__ w) {
    int is64 = 1;
    for (int i = 1; i < 64; i += 2)
        if (w[i] != 0u) { is64 = 0; break; }
    g_is64 = is64;
}
__global__ void loadidx_k(const unsigned *__restrict__ w) {
    int e = blockIdx.x * 256 + threadIdx.x;
    if (e < EE) {
        int s, d;
        if (g_is64) {
            s = (int)w[2 * e];
            d = (int)w[2 * (EE + e)];
        } else {
            s = (int)w[e];
            d = (int)w[EE + e];
        }
        g_src[e] = s & (NNODE - 1);
        g_dstA[e] = d & (NNODE - 1);
    }
}

// ------------- pack A (x) into mma fragments -------------
__global__ void pack_a_k(const float *__restrict__ x) {
    int t = blockIdx.x * 256 + threadIdx.x;  // 32768 threads
    int lane = t & 31, kt = (t >> 5) & 3, mt = t >> 7;
    int gid = lane >> 2, tig = lane & 3;
    int r0 = mt * 16 + gid, r1 = r0 + 8;
    int c0 = kt * 16 + tig * 2, c1 = c0 + 8;
    uint4 hi, lo;
    split2(x[r0 * 64 + c0], x[r0 * 64 + c0 + 1], hi.x, lo.x);
    split2(x[r1 * 64 + c0], x[r1 * 64 + c0 + 1], hi.y, lo.y);
    split2(x[r0 * 64 + c1], x[r0 * 64 + c1 + 1], hi.z, lo.z);
    split2(x[r1 * 64 + c1], x[r1 * 64 + c1 + 1], hi.w, lo.w);
    g_ApackHi[(mt * 4 + kt) * 32 + lane] = hi;
    g_ApackLo[(mt * 4 + kt) * 32 + lane] = lo;
}

// ------------- pack W_l/W_r into B fragments -------------
__global__ void pack_w_k(const float *__restrict__ Wl, const float *__restrict__ Wr) {
    unsigned t = blockIdx.x * 256u + threadIdx.x;  // 1,048,576 threads
    unsigned mat = t >> 19, idx = t & 524287u;
    unsigned kt = idx >> 17, rem = idx & 131071u;
    unsigned n = rem >> 3, j = rem & 7;
    unsigned q = j >> 1, s = j & 1;
    unsigned k = kt * 16 + s * 8 + q * 2;
    const float *W = mat ? Wr : Wl;
    unsigned hi, lo;
    split2(W[k * HC + n], W[(k + 1) * HC + n], hi, lo);
    g_WpackHi[t] = hi;
    g_WpackLo[t] = lo;
}

// ------------- CSR by destination -------------
__global__ void zero_deg_k() {
    int t = blockIdx.x * 256 + threadIdx.x;
    if (t < NNODE) g_deg[t] = 0;
}
__global__ void hist_k() {
    int e = blockIdx.x * 256 + threadIdx.x;
    if (e < EE) atomicAdd(&g_deg[g_dstA[e]], 1);
}
__global__ void scan_k() {
    __shared__ int sm[1024];
    int t = threadIdx.x, b = t * 4;
    int d0 = g_deg[b], d1 = g_deg[b + 1], d2 = g_deg[b + 2], d3 = g_deg[b + 3];
    int p1 = d0, p2 = d0 + d1, p3 = p2 + d2, tot = p3 + d3;
    sm[t] = tot;
    __syncthreads();
    for (int off = 1; off < 1024; off <<= 1) {
        int y = (t >= off) ? sm[t - off] : 0;
        __syncthreads();
        sm[t] += y;
        __syncthreads();
    }
    int excl = (t > 0) ? sm[t - 1] : 0;
    g_rowptr[b] = excl;          g_cursor[b] = excl;
    g_rowptr[b + 1] = excl + p1; g_cursor[b + 1] = excl + p1;
    g_rowptr[b + 2] = excl + p2; g_cursor[b + 2] = excl + p2;
    g_rowptr[b + 3] = excl + p3; g_cursor[b + 3] = excl + p3;
    if (t == 1023) g_rowptr[NNODE] = sm[1023];
}
__global__ void scatter_k() {
    int e = blockIdx.x * 256 + threadIdx.x;
    if (e < EE) {
        int dst = g_dstA[e];
        g_esrc[atomicAdd(&g_cursor[dst], 1)] = g_src[e];
    }
}

// ------------- GEMM: XLR = x @ [W_l | W_r] (bf16 hi/lo split mma, fp16 out) -------------
__global__ void __launch_bounds__(256) gemm_k() {
    __shared__ uint4 sB[1024];
    int t = threadIdx.x;
    int n0 = blockIdx.x * 64;
    int mat = (n0 >= HC) ? 1 : 0;
    int nn = n0 - mat * HC;
    const uint4 *Vh = ((const uint4 *)g_WpackHi) + (size_t)mat * 131072;
    const uint4 *Vl = ((const uint4 *)g_WpackLo) + (size_t)mat * 131072;
#pragma unroll
    for (int i = 0; i < 4; i++) {
        int idx = i * 256 + t;
        int isLo = idx >> 9, w = idx & 511;
        int kt = w >> 7, u = w & 127;
        const uint4 *src = isLo ? Vl : Vh;
        sB[isLo * 512 + kt * 128 + u] = src[(kt * 16384 + nn) * 2 + u];
    }
    int warp = t >> 5, lane = t & 31;
    int gid = lane >> 2, tig = lane & 3;
    int mt = blockIdx.y * 8 + warp;
    uint4 aH[4], aL[4];
#pragma unroll
    for (int kt = 0; kt < 4; kt++) {
        aH[kt] = g_ApackHi[(mt * 4 + kt) * 32 + lane];
        aL[kt] = g_ApackLo[(mt * 4 + kt) * 32 + lane];
    }
    __syncthreads();
    const unsigned *sH = (const unsigned *)sB;
    const unsigned *sL = sH + 2048;
    size_t rowoff = (size_t)(mt * 16 + gid) * 32768 + n0;
    __half *o0 = g_XLRh + rowoff;
    __half *o1 = g_XLRh + rowoff + (size_t)8 * 32768;
#pragma unroll
    for (int nt = 0; nt < 8; nt++) {
        float c0 = 0.f, c1 = 0.f, c2 = 0.f, c3 = 0.f;
#pragma unroll
        for (int kt = 0; kt < 4; kt++) {
            int bi = kt * 512 + (nt * 8 + gid) * 8 + tig * 2;
            unsigned bh0 = sH[bi], bh1 = sH[bi + 1];
            unsigned bl0 = sL[bi], bl1 = sL[bi + 1];
            mma_bf16(c0, c1, c2, c3, aH[kt].x, aH[kt].y, aH[kt].z, aH[kt].w, bh0, bh1);
            mma_bf16(c0, c1, c2, c3, aH[kt].x, aH[kt].y, aH[kt].z, aH[kt].w, bl0, bl1);
            mma_bf16(c0, c1, c2, c3, aL[kt].x, aL[kt].y, aL[kt].z, aL[kt].w, bh0, bh1);
        }
        int col = nt * 8 + tig * 2;
        *(__half2 *)(o0 + col) = __floats2half2_rn(c0, c1);
        *(__half2 *)(o1 + col) = __floats2half2_rn(c2, c3);
    }
}

// ------------- fused attention (fp16 in/out): logits + online softmax + agg + bias + relu
__global__ void __launch_bounds__(128) attn_k(const float *__restrict__ att,
                                              const float *__restrict__ bias) {
    int dst = blockIdx.x, h = blockIdx.y;
    int t = threadIdx.x, warp = t >> 5, lane = t & 31;
    // thread t owns channels [8t, 8t+8)
    const uint4 *xr4 = (const uint4 *)(g_XLRh + (size_t)dst * 32768 + HC + h * 1024);
    float xr[8];
    h8_to_f(xr4[t], xr);
    const float4 *at4 = (const float4 *)(att + h * 1024);
    float4 aA = at4[2 * t], aB = at4[2 * t + 1];
    float at[8] = {aA.x, aA.y, aA.z, aA.w, aB.x, aB.y, aB.z, aB.w};
    float acc[8] = {0.f, 0.f, 0.f, 0.f, 0.f, 0.f, 0.f, 0.f};
    float m = -1e30f, s = 0.f;
    __shared__ float red[4];
    int rp = g_rowptr[dst];
    int deg = g_rowptr[dst + 1] - rp;
    for (int i = 0; i <= deg; i++) {  // last = self-loop
        int src = (i < deg) ? g_esrc[rp + i] : dst;
        const uint4 *xl4 = (const uint4 *)(g_XLRh + (size_t)src * 32768 + h * 1024);
        float xl[8];
        h8_to_f(xl4[t], xl);
        float p = 0.f;
#pragma unroll
        for (int j = 0; j < 8; j++) p = fmaf(at[j], lrelu(xl[j] + xr[j]), p);
        p += __shfl_xor_sync(0xffffffffu, p, 16);
        p += __shfl_xor_sync(0xffffffffu, p, 8);
        p += __shfl_xor_sync(0xffffffffu, p, 4);
        p += __shfl_xor_sync(0xffffffffu, p, 2);
        p += __shfl_xor_sync(0xffffffffu, p, 1);
        if (lane == 0) red[warp] = p;
        __syncthreads();
        float l = red[0] + red[1] + red[2] + red[3];
        float mn = fmaxf(m, l);
        float sc = __expf(m - mn);
        float w = __expf(l - mn);
        s = s * sc + w;
#pragma unroll
        for (int j = 0; j < 8; j++) acc[j] = fmaf(acc[j], sc, w * xl[j]);
        m = mn;
        __syncthreads();
    }
    float inv = 1.f / (s + 1e-16f);
    const float4 *b4 = (const float4 *)(bias + h * 1024);
    float4 bA = b4[2 * t], bB = b4[2 * t + 1];
    float bi[8] = {bA.x, bA.y, bA.z, bA.w, bB.x, bB.y, bB.z, bB.w};
    uint4 ou;
    __half2 *op = (__half2 *)&ou;
#pragma unroll
    for (int j = 0; j < 4; j++) {
        float v0 = fmaxf(fmaf(acc[2 * j], inv, bi[2 * j]), 0.f);
        float v1 = fmaxf(fmaf(acc[2 * j + 1], inv, bi[2 * j + 1]), 0.f);
        op[j] = __floats2half2_rn(v0, v1);
    }
    ((uint4 *)(g_Rh + (size_t)dst * HC + h * 1024))[t] = ou;
}

// ------------- output GEMM: z = R @ W_out + b_out -------------
__global__ void zinit_k(float *__restrict__ out, const float *__restrict__ bout) {
    int i = blockIdx.x * 256 + threadIdx.x;  // 81920 exactly
    out[i] = bout[i % 20];
}
__global__ void __launch_bounds__(128) zout_k(const float *__restrict__ Wout,
                                              float *__restrict__ out) {
    __shared__ float4 sW[640];  // 128 k-rows x 20 floats
    int t = threadIdx.x;
    int row0 = blockIdx.x * 256 + t;  // rows row0, row0+128
    int kb = blockIdx.y * 2048;
    float acc0[20], acc1[20];
#pragma unroll
    for (int j = 0; j < 20; j++) { acc0[j] = 0.f; acc1[j] = 0.f; }
    const uint4 *R0 = (const uint4 *)(g_Rh + (size_t)row0 * HC + kb);
    const uint4 *R1 = (const uint4 *)(g_Rh + (size_t)(row0 + 128) * HC + kb);
    for (int ch = 0; ch < 16; ch++) {
        __syncthreads();
        const float4 *Wg = (const float4 *)(Wout + (size_t)(kb + ch * 128) * 20);
        for (int i = t; i < 640; i += 128) sW[i] = Wg[i];
        __syncthreads();
#pragma unroll 2
        for (int i8 = 0; i8 < 16; i8++) {  // 8 k-values per uint4
            float r0[8], r1[8];
            h8_to_f(R0[ch * 16 + i8], r0);
            h8_to_f(R1[ch * 16 + i8], r1);
            const float4 *wrow = sW + (i8 * 8) * 5;
#pragma unroll
            for (int kk = 0; kk < 8; kk++) {
                float a = r0[kk], b = r1[kk];
#pragma unroll
                for (int q = 0; q < 5; q++) {
                    float4 w = wrow[kk * 5 + q];
                    acc0[q * 4 + 0] = fmaf(a, w.x, acc0[q * 4 + 0]);
                    acc0[q * 4 + 1] = fmaf(a, w.y, acc0[q * 4 + 1]);
                    acc0[q * 4 + 2] = fmaf(a, w.z, acc0[q * 4 + 2]);
                    acc0[q * 4 + 3] = fmaf(a, w.w, acc0[q * 4 + 3]);
                    acc1[q * 4 + 0] = fmaf(b, w.x, acc1[q * 4 + 0]);
                    acc1[q * 4 + 1] = fmaf(b, w.y, acc1[q * 4 + 1]);
                    acc1[q * 4 + 2] = fmaf(b, w.z, acc1[q * 4 + 2]);
                    acc1[q * 4 + 3] = fmaf(b, w.w, acc1[q * 4 + 3]);
                }
            }
        }
    }
#pragma unroll
    for (int j = 0; j < 20; j++) {
        atomicAdd(&out[row0 * 20 + j], acc0[j]);
        atomicAdd(&out[(row0 + 128) * 20 + j], acc1[j]);
    }
}

extern "C" void kernel_launch(void *const *d_in, const int *in_sizes, int n_in,
                              void *d_out, int out_size) {
    const float *x = (const float *)d_in[0];
    const unsigned *ei = (const unsigned *)d_in[1];
    const float *Wl = (const float *)d_in[2];
    const float *Wr = (const float *)d_in[3];
    const float *att = (const float *)d_in[4];
    const float *bias = (const float *)d_in[5];
    const float *Wout = (const float *)d_in[6];
    const float *bout = (const float *)d_in[7];
    float *out = (float *)d_out;

    detect_k<<<1, 1>>>(ei);
    loadidx_k<<<64, 256>>>(ei);
    pack_a_k<<<128, 256>>>(x);
    pack_w_k<<<4096, 256>>>(Wl, Wr);
    zero_deg_k<<<16, 256>>>();
    hist_k<<<64, 256>>>();
    scan_k<<<1, 1024>>>();
    scatter_k<<<64, 256>>>();
    gemm_k<<<dim3(512, 32), 256>>>();
    zinit_k<<<320, 256>>>(out, bout);
    attn_k<<<dim3(4096, 16), 128>>>(att, bias);
    zout_k<<<dim3(16, 8), 128>>>(Wout, out);
}